// round 7
// baseline (speedup 1.0000x reference)
#include <cuda_runtime.h>
#include <math.h>
#include <stdint.h>

#define DIM      768
#define HEADS    12
#define HD       64
#define HIDDEN   3072
#define SEQ      577
#define BATCH    64
#define NTOK     (BATCH*SEQ)  // 36928
#define QKVD     (3*DIM)      // 2304

// expanded row pitches in 32-bit words: K*3/2
#define AXP      1152         // K=768  -> 1152 words (4608 B)
#define MXP      4608         // K=3072 -> 4608 words (18432 B)

// ---------------- single scratch arena ----------------
#define QKV_F   ((size_t)NTOK * QKVD)
#define X2_F    ((size_t)NTOK * DIM)
#define AX_W    ((size_t)NTOK * AXP)
#define MX_W    ((size_t)NTOK * MXP)
#define WQKV_W  ((size_t)QKVD * AXP)
#define WPROJ_W ((size_t)DIM * AXP)
#define W1X_W   ((size_t)HIDDEN * AXP)
#define W2X_W   ((size_t)DIM * MXP)
#define ARENA_WORDS (QKV_F + X2_F + AX_W + MX_W + WQKV_W + WPROJ_W + W1X_W + W2X_W)
__device__ uint32_t g_arena[ARENA_WORDS];

// ---------------- helpers ----------------
__device__ __forceinline__ uint32_t smem_u32(const void* p) {
    uint32_t a;
    asm("{ .reg .u64 t; cvta.to.shared.u64 t, %1; cvt.u32.u64 %0, t; }"
        : "=r"(a) : "l"(p));
    return a;
}
__device__ __forceinline__ uint32_t bf16h(float f) {
    uint32_t u = __float_as_uint(f);
    return (u + 0x7FFFu + ((u >> 16) & 1u)) >> 16;
}
__device__ __forceinline__ float bf16f(uint32_t h) {
    return __uint_as_float(h << 16);
}
// A-pattern for value pair (v0,v1): slots [h0,h0,l0, h1,h1,l1]
__device__ __forceinline__ void packA(float v0, float v1, uint32_t* w) {
    const uint32_t h0 = bf16h(v0), l0 = bf16h(v0 - bf16f(h0));
    const uint32_t h1 = bf16h(v1), l1 = bf16h(v1 - bf16f(h1));
    w[0] = h0 | (h0 << 16);
    w[1] = l0 | (h1 << 16);
    w[2] = h1 | (l1 << 16);
}
// B-pattern for value pair (v0,v1): slots [h0,l0,h0, h1,l1,h1]
__device__ __forceinline__ void packB(float v0, float v1, uint32_t* w) {
    const uint32_t h0 = bf16h(v0), l0 = bf16h(v0 - bf16f(h0));
    const uint32_t h1 = bf16h(v1), l1 = bf16h(v1 - bf16f(h1));
    w[0] = h0 | (l0 << 16);
    w[1] = h0 | (h1 << 16);
    w[2] = l1 | (h1 << 16);
}

#define LDSM4(r0, r1, r2, r3, addr) \
    asm volatile("ldmatrix.sync.aligned.m8n8.x4.shared.b16 {%0,%1,%2,%3}, [%4];" \
                 : "=r"(r0), "=r"(r1), "=r"(r2), "=r"(r3) : "r"(addr))

#define MMA_BF16(d, a, b) \
    asm volatile("mma.sync.aligned.m16n8k16.row.col.f32.bf16.bf16.f32 " \
                 "{%0,%1,%2,%3}, {%4,%5,%6,%7}, {%8,%9}, {%0,%1,%2,%3};" \
                 : "+f"((d)[0]), "+f"((d)[1]), "+f"((d)[2]), "+f"((d)[3]) \
                 : "r"((a)[0]), "r"((a)[1]), "r"((a)[2]), "r"((a)[3]), \
                   "r"((b)[0]), "r"((b)[1]))

#define CP16(dst, src, sz) \
    asm volatile("cp.async.cg.shared.global [%0], [%1], 16, %2;" \
                 :: "r"(dst), "l"(src), "r"(sz))
#define CP_COMMIT() asm volatile("cp.async.commit_group;")
#define CP_WAIT1()  asm volatile("cp.async.wait_group 1;")

// ============ bf16-split tensor-core GEMM, pre-expanded operands ============
// Ax [M rows, K*3/2 words] (A-pattern), Bx [N rows, K*3/2 words] (B-pattern).
// Tile 128x128, k-block = 32 floats = 48 words = 192 B per row.
#define PITCHB   208
#define TILEB    (128 * PITCHB)
#define BUFB     (2 * TILEB)
#define GEMM_SMEM (2 * BUFB)     // 106496

template<bool BIAS, bool GELU, bool RES, bool OUTX>
__global__ __launch_bounds__(256) void tcgemm_kernel(
    const uint32_t* __restrict__ Ax, const uint32_t* __restrict__ Bx,
    const float* __restrict__ bias, const float* __restrict__ res,
    float* __restrict__ C, uint32_t* __restrict__ Cx,
    int M, int N, int K)
{
    extern __shared__ char smem[];
    const uint32_t sb = smem_u32(smem);
    const int tid  = threadIdx.x;
    const int lane = tid & 31;
    const int wid  = tid >> 5;
    const int wr = wid >> 2, wc = wid & 3;
    const int m0w = wr * 64, n0w = wc * 32;

    const int m0 = blockIdx.y * 128, col0 = blockIdx.x * 128;
    const int KW = (K >> 1) * 3;          // words per expanded row
    const int NBLK = K >> 5;

    // loader: row = tid/2 (0..127), half = tid&1 covers 96 B
    const int row = tid >> 1, half = tid & 1;
    const int gar = m0 + row;
    const uint32_t asz = (gar < M) ? 16u : 0u;
    const uint32_t* gA = Ax + (size_t)(gar < M ? gar : M - 1) * KW + half * 24;
    const uint32_t* gB = Bx + (size_t)(col0 + row) * KW + half * 24;
    const uint32_t dA = sb + row * PITCHB + half * 96;
    const uint32_t dB = sb + TILEB + row * PITCHB + half * 96;

    float dacc[16][4];
    #pragma unroll
    for (int t = 0; t < 16; t++)
        #pragma unroll
        for (int c = 0; c < 4; c++) dacc[t][c] = 0.f;

    // prologue: blocks 0,1
    {
        #pragma unroll
        for (int i = 0; i < 6; i++) {
            CP16(dA + i * 16, gA + i * 4, asz);
            CP16(dB + i * 16, gB + i * 4, 16u);
        }
        CP_COMMIT();
        if (NBLK > 1) {
            #pragma unroll
            for (int i = 0; i < 6; i++) {
                CP16(dA + BUFB + i * 16, gA + 48 + i * 4, asz);
                CP16(dB + BUFB + i * 16, gB + 48 + i * 4, 16u);
            }
        }
        CP_COMMIT();
    }

    int buf = 0;
    for (int blk = 0; blk < NBLK; blk++) {
        CP_WAIT1();
        __syncthreads();

        const uint32_t sA  = sb + buf * BUFB;
        const uint32_t sBB = sA + TILEB;
        const uint32_t aAddrBase = sA + (uint32_t)(m0w + (lane & 15)) * PITCHB
                                      + ((lane >> 4) * 8) * 2;
        const int g = lane >> 3;
        const uint32_t bAddrBase = sBB + (uint32_t)(n0w + ((g >> 1) * 8) + (lane & 7)) * PITCHB
                                       + ((g & 1) * 8) * 2;
        #pragma unroll
        for (int kc = 0; kc < 6; kc++) {
            uint32_t af[4][4], bfr[4][2];
            #pragma unroll
            for (int mi = 0; mi < 4; mi++)
                LDSM4(af[mi][0], af[mi][1], af[mi][2], af[mi][3],
                      aAddrBase + (uint32_t)mi * 16 * PITCHB + kc * 32);
            LDSM4(bfr[0][0], bfr[0][1], bfr[1][0], bfr[1][1], bAddrBase + kc * 32);
            LDSM4(bfr[2][0], bfr[2][1], bfr[3][0], bfr[3][1],
                  bAddrBase + 16 * PITCHB + kc * 32);
            #pragma unroll
            for (int mi = 0; mi < 4; mi++)
                #pragma unroll
                for (int nt = 0; nt < 4; nt++)
                    MMA_BF16(dacc[mi * 4 + nt], af[mi], bfr[nt]);
        }

        __syncthreads();
        if (blk + 2 < NBLK) {
            const uint32_t* a = gA + (blk + 2) * 48;
            const uint32_t* b = gB + (blk + 2) * 48;
            const uint32_t bo = buf * BUFB;
            #pragma unroll
            for (int i = 0; i < 6; i++) {
                CP16(dA + bo + i * 16, a + i * 4, asz);
                CP16(dB + bo + i * 16, b + i * 4, 16u);
            }
        }
        CP_COMMIT();
        buf ^= 1;
    }

    // ---- epilogue ----
    const int OXP = OUTX ? (N >> 1) * 3 : 0;
    #pragma unroll
    for (int mi = 0; mi < 4; mi++) {
        const int r0 = m0 + m0w + mi * 16 + (lane >> 2);
        #pragma unroll
        for (int nt = 0; nt < 4; nt++) {
            const int c = col0 + n0w + nt * 8 + (lane & 3) * 2;
            const float* d = dacc[mi * 4 + nt];
            float b0 = 0.f, b1 = 0.f;
            if (BIAS) { b0 = bias[c]; b1 = bias[c + 1]; }
            #pragma unroll
            for (int hf = 0; hf < 2; hf++) {
                const int r = r0 + hf * 8;
                if (r >= M) continue;
                float v0 = d[hf * 2 + 0] + b0;
                float v1 = d[hf * 2 + 1] + b1;
                if (GELU) {
                    v0 = 0.5f * v0 * (1.0f + erff(v0 * 0.70710678118654752f));
                    v1 = 0.5f * v1 * (1.0f + erff(v1 * 0.70710678118654752f));
                }
                if (RES) {
                    const float2 rv = *reinterpret_cast<const float2*>(
                        res + (size_t)r * N + c);
                    v0 += rv.x; v1 += rv.y;
                }
                if (OUTX) {
                    uint32_t w[3];
                    packA(v0, v1, w);
                    uint32_t* o = Cx + (size_t)r * OXP + (c >> 1) * 3;
                    o[0] = w[0]; o[1] = w[1]; o[2] = w[2];
                } else {
                    *reinterpret_cast<float2*>(C + (size_t)r * N + c) =
                        make_float2(v0, v1);
                }
            }
        }
    }
}

// ---------------- weight expand: W [K,N] f32 -> Wx [N][K*3/2 w] B-pattern ----
__global__ __launch_bounds__(256) void splitw_kernel(
    const float* __restrict__ W, uint32_t* __restrict__ Wx, int K, int N)
{
    const int idx = blockIdx.x * 256 + threadIdx.x;
    const int total = N * (K >> 1);
    if (idx >= total) return;
    const int n = idx % N, p = idx / N;
    const float v0 = W[(size_t)(2 * p) * N + n];
    const float v1 = W[(size_t)(2 * p + 1) * N + n];
    uint32_t w[3];
    packB(v0, v1, w);
    uint32_t* o = Wx + (size_t)n * ((K >> 1) * 3) + p * 3;
    o[0] = w[0]; o[1] = w[1]; o[2] = w[2];
}

// ---------------- LayerNorm -> expanded A rows (192 thr, float4/thread) ------
__global__ __launch_bounds__(192) void lnx_kernel(
    const float* __restrict__ x, const float* __restrict__ g,
    const float* __restrict__ b, uint32_t* __restrict__ out)
{
    const size_t t = blockIdx.x;
    const int tid = threadIdx.x;
    const float4 v = *reinterpret_cast<const float4*>(x + t * DIM + tid * 4);

    float s  = v.x + v.y + v.z + v.w;
    float ss = v.x*v.x + v.y*v.y + v.z*v.z + v.w*v.w;

    __shared__ float red[12];
    __shared__ float stat[2];
    #pragma unroll
    for (int o = 16; o; o >>= 1) {
        s  += __shfl_xor_sync(0xffffffffu, s,  o);
        ss += __shfl_xor_sync(0xffffffffu, ss, o);
    }
    if ((tid & 31) == 0) { red[tid >> 5] = s; red[(tid >> 5) + 6] = ss; }
    __syncthreads();
    if (tid == 0) {
        float a = 0.f, c = 0.f;
        #pragma unroll
        for (int i = 0; i < 6; i++) { a += red[i]; c += red[i + 6]; }
        const float mu = a * (1.0f / DIM);
        stat[0] = mu;
        stat[1] = rsqrtf(c * (1.0f / DIM) - mu * mu + 1e-5f);
    }
    __syncthreads();
    const float mu = stat[0], inv = stat[1];

    const float4 g4 = *reinterpret_cast<const float4*>(g + tid * 4);
    const float4 b4 = *reinterpret_cast<const float4*>(b + tid * 4);
    const float n0 = (v.x - mu) * inv * g4.x + b4.x;
    const float n1 = (v.y - mu) * inv * g4.y + b4.y;
    const float n2 = (v.z - mu) * inv * g4.z + b4.z;
    const float n3 = (v.w - mu) * inv * g4.w + b4.w;

    uint32_t w[6];
    packA(n0, n1, w);
    packA(n2, n3, w + 3);
    uint32_t* o = out + t * AXP + tid * 6;
    *reinterpret_cast<uint2*>(o)     = make_uint2(w[0], w[1]);
    *reinterpret_cast<uint2*>(o + 2) = make_uint2(w[2], w[3]);
    *reinterpret_cast<uint2*>(o + 4) = make_uint2(w[4], w[5]);
}

// ---------------- Fused flash attention -> expanded O ----------------
#define FA_SMEM (3 * 64 * 68 * 4)

__global__ __launch_bounds__(256) void fattn_kernel(
    const float* __restrict__ qkv, uint32_t* __restrict__ Ox)
{
    extern __shared__ float sm[];
    float (*Qs)[68] = reinterpret_cast<float(*)[68]>(sm);
    float (*KP)[68] = reinterpret_cast<float(*)[68]>(sm + 64 * 68);
    float (*Vs)[68] = reinterpret_cast<float(*)[68]>(sm + 2 * 64 * 68);

    const int bh = blockIdx.y;
    const int b = bh / HEADS, h = bh % HEADS;
    const int n0 = blockIdx.x * 64;
    const float* qb = qkv + (size_t)b * SEQ * QKVD + h * HD;
    const float* kb = qb + DIM;
    const float* vb = qb + 2 * DIM;

    const int tid = threadIdx.x;
    const int lr = tid >> 2;
    const int lc = (tid & 3) * 16;
    const int tx = tid & 15, ty = tid >> 4;

    {
        const int n = n0 + lr;
        const float4* src = (n < SEQ)
            ? reinterpret_cast<const float4*>(qb + (size_t)n * QKVD + lc) : nullptr;
        #pragma unroll
        for (int c4 = 0; c4 < 4; c4++) {
            float4 v = src ? src[c4] : make_float4(0.f,0.f,0.f,0.f);
            const int d = lc + c4 * 4;
            Qs[d][lr]=v.x; Qs[d+1][lr]=v.y; Qs[d+2][lr]=v.z; Qs[d+3][lr]=v.w;
        }
    }

    float acc_o[4][4];
    float row_m[4], row_l[4];
    #pragma unroll
    for (int i = 0; i < 4; i++) {
        row_m[i] = -1e30f; row_l[i] = 0.f;
        #pragma unroll
        for (int j = 0; j < 4; j++) acc_o[i][j] = 0.f;
    }

    for (int k0 = 0; k0 < SEQ; k0 += 64) {
        __syncthreads();
        {
            const int m = k0 + lr;
            const float4* srck = (m < SEQ)
                ? reinterpret_cast<const float4*>(kb + (size_t)m * QKVD + lc) : nullptr;
            const float4* srcv = (m < SEQ)
                ? reinterpret_cast<const float4*>(vb + (size_t)m * QKVD + lc) : nullptr;
            #pragma unroll
            for (int c4 = 0; c4 < 4; c4++) {
                float4 v = srck ? srck[c4] : make_float4(0.f,0.f,0.f,0.f);
                const int d = lc + c4 * 4;
                KP[d][lr]=v.x; KP[d+1][lr]=v.y; KP[d+2][lr]=v.z; KP[d+3][lr]=v.w;
                float4 w = srcv ? srcv[c4] : make_float4(0.f,0.f,0.f,0.f);
                *reinterpret_cast<float4*>(&Vs[lr][lc + c4 * 4]) = w;
            }
        }
        __syncthreads();

        float s[4][4];
        #pragma unroll
        for (int i = 0; i < 4; i++)
            #pragma unroll
            for (int j = 0; j < 4; j++) s[i][j] = 0.f;

        #pragma unroll 8
        for (int d = 0; d < 64; d++) {
            float4 ra = *reinterpret_cast<const float4*>(&Qs[d][ty * 4]);
            float4 rb = *reinterpret_cast<const float4*>(&KP[d][tx * 4]);
            float a[4] = {ra.x, ra.y, ra.z, ra.w};
            float bb[4] = {rb.x, rb.y, rb.z, rb.w};
            #pragma unroll
            for (int i = 0; i < 4; i++)
                #pragma unroll
                for (int j = 0; j < 4; j++)
                    s[i][j] = fmaf(a[i], bb[j], s[i][j]);
        }

        #pragma unroll
        for (int i = 0; i < 4; i++)
            #pragma unroll
            for (int j = 0; j < 4; j++) {
                s[i][j] *= 0.125f;
                if (k0 + tx * 4 + j >= SEQ) s[i][j] = -1e30f;
            }

        float f[4];
        #pragma unroll
        for (int i = 0; i < 4; i++) {
            float mt = fmaxf(fmaxf(s[i][0], s[i][1]), fmaxf(s[i][2], s[i][3]));
            #pragma unroll
            for (int o = 1; o < 16; o <<= 1)
                mt = fmaxf(mt, __shfl_xor_sync(0xffffffffu, mt, o, 16));
            const float nm = fmaxf(row_m[i], mt);
            f[i] = __expf(row_m[i] - nm);
            row_m[i] = nm;
            float rs = 0.f;
            #pragma unroll
            for (int j = 0; j < 4; j++) {
                s[i][j] = __expf(s[i][j] - nm);
                rs += s[i][j];
            }
            #pragma unroll
            for (int o = 1; o < 16; o <<= 1)
                rs += __shfl_xor_sync(0xffffffffu, rs, o, 16);
            row_l[i] = row_l[i] * f[i] + rs;
            #pragma unroll
            for (int j = 0; j < 4; j++) acc_o[i][j] *= f[i];
        }

        __syncthreads();
        #pragma unroll
        for (int i = 0; i < 4; i++)
            *reinterpret_cast<float4*>(&KP[ty * 4 + i][tx * 4]) =
                make_float4(s[i][0], s[i][1], s[i][2], s[i][3]);
        __syncthreads();

        #pragma unroll 4
        for (int k = 0; k < 64; k += 4) {
            float4 pa[4], vv[4];
            #pragma unroll
            for (int i = 0; i < 4; i++)
                pa[i] = *reinterpret_cast<const float4*>(&KP[ty * 4 + i][k]);
            #pragma unroll
            for (int kk = 0; kk < 4; kk++)
                vv[kk] = *reinterpret_cast<const float4*>(&Vs[k + kk][tx * 4]);
            #pragma unroll
            for (int i = 0; i < 4; i++) {
                float p[4] = {pa[i].x, pa[i].y, pa[i].z, pa[i].w};
                #pragma unroll
                for (int kk = 0; kk < 4; kk++) {
                    acc_o[i][0] = fmaf(p[kk], vv[kk].x, acc_o[i][0]);
                    acc_o[i][1] = fmaf(p[kk], vv[kk].y, acc_o[i][1]);
                    acc_o[i][2] = fmaf(p[kk], vv[kk].z, acc_o[i][2]);
                    acc_o[i][3] = fmaf(p[kk], vv[kk].w, acc_o[i][3]);
                }
            }
        }
    }

    #pragma unroll
    for (int i = 0; i < 4; i++) {
        const int n = n0 + ty * 4 + i;
        if (n >= SEQ) continue;
        const float inv = 1.0f / row_l[i];
        uint32_t w[6];
        packA(acc_o[i][0] * inv, acc_o[i][1] * inv, w);
        packA(acc_o[i][2] * inv, acc_o[i][3] * inv, w + 3);
        uint32_t* o = Ox + (size_t)(b * SEQ + n) * AXP + (h * 32 + tx * 2) * 3;
        *reinterpret_cast<uint2*>(o)     = make_uint2(w[0], w[1]);
        *reinterpret_cast<uint2*>(o + 2) = make_uint2(w[2], w[3]);
        *reinterpret_cast<uint2*>(o + 4) = make_uint2(w[4], w[5]);
    }
}

// ---------------- launch ----------------
extern "C" void kernel_launch(void* const* d_in, const int* in_sizes, int n_in,
                              void* d_out, int out_size)
{
    const float* x     = (const float*)d_in[0];
    const float* ln1_g = (const float*)d_in[1];
    const float* ln1_b = (const float*)d_in[2];
    const float* Wqkv  = (const float*)d_in[3];
    const float* Wproj = (const float*)d_in[4];
    const float* bproj = (const float*)d_in[5];
    const float* ln2_g = (const float*)d_in[6];
    const float* ln2_b = (const float*)d_in[7];
    const float* W1    = (const float*)d_in[8];
    const float* b1    = (const float*)d_in[9];
    const float* W2    = (const float*)d_in[10];
    const float* b2    = (const float*)d_in[11];
    float* out = (float*)d_out;

    void* p_arena;
    cudaGetSymbolAddress(&p_arena, g_arena);
    uint32_t* arena = (uint32_t*)p_arena;
    float*    qkvb  = (float*)arena;                         // QKV_F
    float*    x2buf = (float*)(arena + QKV_F);               // X2_F
    uint32_t* axb   = arena + QKV_F + X2_F;                  // AX_W
    uint32_t* mxb   = axb + AX_W;                            // MX_W
    uint32_t* wqkvx = mxb + MX_W;                            // WQKV_W
    uint32_t* wprojx= wqkvx + WQKV_W;                        // WPROJ_W
    uint32_t* w1x   = wprojx + WPROJ_W;                      // W1X_W
    uint32_t* w2x   = w1x + W1X_W;                           // W2X_W

    cudaFuncSetAttribute(fattn_kernel,
                         cudaFuncAttributeMaxDynamicSharedMemorySize, FA_SMEM);
    cudaFuncSetAttribute(tcgemm_kernel<false,false,false,false>,
                         cudaFuncAttributeMaxDynamicSharedMemorySize, GEMM_SMEM);
    cudaFuncSetAttribute(tcgemm_kernel<true,false,true,false>,
                         cudaFuncAttributeMaxDynamicSharedMemorySize, GEMM_SMEM);
    cudaFuncSetAttribute(tcgemm_kernel<true,true,false,true>,
                         cudaFuncAttributeMaxDynamicSharedMemorySize, GEMM_SMEM);

    const int MT = (NTOK + 127) / 128;  // 289

    // 0. expand weights (once per launch)
    splitw_kernel<<<(QKVD * (DIM/2) + 255) / 256, 256>>>(Wqkv, wqkvx, DIM, QKVD);
    splitw_kernel<<<(DIM * (DIM/2) + 255) / 256, 256>>>(Wproj, wprojx, DIM, DIM);
    splitw_kernel<<<(HIDDEN * (DIM/2) + 255) / 256, 256>>>(W1, w1x, DIM, HIDDEN);
    splitw_kernel<<<(DIM * (HIDDEN/2) + 255) / 256, 256>>>(W2, w2x, HIDDEN, DIM);

    // 1. ax = expand(LN1(x))
    lnx_kernel<<<NTOK, 192>>>(x, ln1_g, ln1_b, axb);
    // 2. qkv = ax @ wqkvx
    tcgemm_kernel<false,false,false,false><<<dim3(QKVD/128, MT), 256, GEMM_SMEM>>>(
        axb, wqkvx, nullptr, nullptr, qkvb, nullptr, NTOK, QKVD, DIM);
    // 3. fused attention -> axb (expanded; ln1 data dead)
    fattn_kernel<<<dim3(10, BATCH*HEADS), 256, FA_SMEM>>>(qkvb, axb);
    // 4. x2 = x + O @ wprojx + bproj
    tcgemm_kernel<true,false,true,false><<<dim3(DIM/128, MT), 256, GEMM_SMEM>>>(
        axb, wprojx, bproj, x, x2buf, nullptr, NTOK, DIM, DIM);
    // 5. ax = expand(LN2(x2))
    lnx_kernel<<<NTOK, 192>>>(x2buf, ln2_g, ln2_b, axb);
    // 6. mx = expand(gelu(ax @ w1x + b1))
    tcgemm_kernel<true,true,false,true><<<dim3(HIDDEN/128, MT), 256, GEMM_SMEM>>>(
        axb, w1x, b1, nullptr, nullptr, mxb, NTOK, HIDDEN, DIM);
    // 7. out = x2 + mx @ w2x + b2
    tcgemm_kernel<true,false,true,false><<<dim3(DIM/128, MT), 256, GEMM_SMEM>>>(
        mxb, w2x, b2, x2buf, out, nullptr, NTOK, DIM, HIDDEN);
}

// round 10
// speedup vs baseline: 1.1711x; 1.1711x over previous
#include <cuda_runtime.h>
#include <math.h>
#include <stdint.h>

#define DIM      768
#define HEADS    12
#define HD       64
#define HIDDEN   3072
#define SEQ      577
#define BATCH    64
#define NTOK     (BATCH*SEQ)  // 36928
#define QKVD     (3*DIM)      // 2304

// expanded weight row pitch in 32-bit words: K*3/2
#define WAXP     1152         // K=768
#define WMXP     4608         // K=3072

// ---------------- scratch arena ----------------
#define H_F     ((size_t)NTOK * DIM)
#define X2_F    ((size_t)NTOK * DIM)
#define OVL_F   ((size_t)NTOK * HIDDEN)          // max(qkv, m)
#define WQKV_W  ((size_t)QKVD * WAXP)
#define WPROJ_W ((size_t)DIM * WAXP)
#define W1X_W   ((size_t)HIDDEN * WAXP)
#define W2X_W   ((size_t)DIM * WMXP)
#define ARENA_WORDS (H_F + X2_F + OVL_F + WQKV_W + WPROJ_W + W1X_W + W2X_W)
__device__ __align__(16) uint32_t g_arena[ARENA_WORDS];

// ---------------- helpers ----------------
__device__ __forceinline__ uint32_t smem_u32(const void* p) {
    uint32_t a;
    asm("{ .reg .u64 t; cvta.to.shared.u64 t, %1; cvt.u32.u64 %0, t; }"
        : "=r"(a) : "l"(p));
    return a;
}
__device__ __forceinline__ uint32_t bf16h(float f) {
    uint32_t u = __float_as_uint(f);
    return (u + 0x7FFFu + ((u >> 16) & 1u)) >> 16;
}
__device__ __forceinline__ float bf16f(uint32_t h) {
    return __uint_as_float(h << 16);
}
// B-pattern for value pair (v0,v1): slots [h0,l0,h0, h1,l1,h1]
__device__ __forceinline__ void packB(float v0, float v1, uint32_t* w) {
    const uint32_t h0 = bf16h(v0), l0 = bf16h(v0 - bf16f(h0));
    const uint32_t h1 = bf16h(v1), l1 = bf16h(v1 - bf16f(h1));
    w[0] = h0 | (l0 << 16);
    w[1] = h0 | (h1 << 16);
    w[2] = l1 | (h1 << 16);
}

#define LDSM4(r0, r1, r2, r3, addr) \
    asm volatile("ldmatrix.sync.aligned.m8n8.x4.shared.b16 {%0,%1,%2,%3}, [%4];" \
                 : "=r"(r0), "=r"(r1), "=r"(r2), "=r"(r3) : "r"(addr))

#define MMA_BF16(d, a, b) \
    asm volatile("mma.sync.aligned.m16n8k16.row.col.f32.bf16.bf16.f32 " \
                 "{%0,%1,%2,%3}, {%4,%5,%6,%7}, {%8,%9}, {%0,%1,%2,%3};" \
                 : "+f"((d)[0]), "+f"((d)[1]), "+f"((d)[2]), "+f"((d)[3]) \
                 : "r"((a)[0]), "r"((a)[1]), "r"((a)[2]), "r"((a)[3]), \
                   "r"((b)[0]), "r"((b)[1]))

#define CP16(dst, src) \
    asm volatile("cp.async.cg.shared.global [%0], [%1], 16;" \
                 :: "r"(dst), "l"(src))
#define CP_COMMIT() asm volatile("cp.async.commit_group;")
#define CP_WAIT0()  asm volatile("cp.async.wait_group 0;")

// ============ bf16-split tensor-core GEMM ============
// A [M,K] fp32 rm (converted in-kernel, A-pattern [h,h,l]).
// Bx [N rows, K*3/2 words] pre-expanded B-pattern [h,l,h].
// Tile 128x128, k-block 32 floats (=48 words = 192 B expanded per row).
#define PITCHB   208
#define TILEB    (128 * PITCHB)
#define BUFB     (2 * TILEB)
#define GEMM_SMEM (2 * BUFB)     // 106496

template<bool BIAS, bool GELU, bool RES>
__global__ __launch_bounds__(256) void tcgemm_kernel(
    const float* __restrict__ A, const uint32_t* __restrict__ Bx,
    const float* __restrict__ bias, const float* __restrict__ res,
    float* __restrict__ C, int M, int N, int K)
{
    extern __shared__ char smem[];
    const uint32_t sb = smem_u32(smem);
    const int tid  = threadIdx.x;
    const int lane = tid & 31;
    const int wid  = tid >> 5;
    const int wr = wid >> 2, wc = wid & 3;
    const int m0w = wr * 64, n0w = wc * 32;

    const int m0 = blockIdx.y * 128, col0 = blockIdx.x * 128;
    const int KW = (K >> 1) * 3;
    const int NBLK = K >> 5;

    // A loader: row = tid/2, seg = tid&1 covers 16 floats -> 96 B expanded
    const int arow = tid >> 1, aseg = tid & 1;
    const int gar = m0 + arow;
    const bool aval = (gar < M);
    const float* Ap = A + (size_t)gar * K + aseg * 16;
    const uint32_t dA = sb + arow * PITCHB + aseg * 96;

    // B loader: same row mapping, cp.async 96 B from expanded weights
    const uint32_t* gB = Bx + (size_t)(col0 + arow) * KW + aseg * 24;
    const uint32_t dB = sb + TILEB + arow * PITCHB + aseg * 96;

    float dacc[16][4];
    #pragma unroll
    for (int t = 0; t < 16; t++)
        #pragma unroll
        for (int c = 0; c < 4; c++) dacc[t][c] = 0.f;

    // convert+store 16 floats of A into buffer offset bufo (scalar stores:
    // 12-byte record stride is NOT 8B-aligned, so no vector smem stores here)
    auto storeA = [&](uint32_t bufo, const float4 a4[4]) {
        const uint32_t dst = dA + bufo;
        #pragma unroll
        for (int q = 0; q < 4; q++) {
            const float v[4] = {a4[q].x, a4[q].y, a4[q].z, a4[q].w};
            #pragma unroll
            for (int pp = 0; pp < 2; pp++) {
                const float v0 = v[pp*2], v1 = v[pp*2+1];
                const uint32_t h0 = bf16h(v0);
                const uint32_t l0 = bf16h(v0 - bf16f(h0));
                const uint32_t h1 = bf16h(v1);
                const uint32_t l1 = bf16h(v1 - bf16f(h1));
                const uint32_t w0 = h0 | (h0 << 16);
                const uint32_t w1 = l0 | (h1 << 16);
                const uint32_t w2 = h1 | (l1 << 16);
                const uint32_t a = dst + (q * 2 + pp) * 12;
                asm volatile("st.shared.b32 [%0], %1;" :: "r"(a),     "r"(w0));
                asm volatile("st.shared.b32 [%0], %1;" :: "r"(a + 4), "r"(w1));
                asm volatile("st.shared.b32 [%0], %1;" :: "r"(a + 8), "r"(w2));
            }
        }
    };

    // ---- prologue: block 0 ----
    {
        float4 a4[4];
        #pragma unroll
        for (int q = 0; q < 4; q++)
            a4[q] = aval ? *reinterpret_cast<const float4*>(Ap + q * 4)
                         : make_float4(0.f, 0.f, 0.f, 0.f);
        storeA(0, a4);
        #pragma unroll
        for (int i = 0; i < 6; i++) CP16(dB + i * 16, gB + i * 4);
        CP_COMMIT();
        CP_WAIT0();
    }
    __syncthreads();

    int buf = 0;
    for (int blk = 0; blk < NBLK; blk++) {
        const bool more = (blk + 1 < NBLK);
        // issue next B into the idle buffer right away (lands during compute)
        if (more) {
            const uint32_t* b = gB + (blk + 1) * 48;
            const uint32_t bo = (buf ^ 1) * BUFB;
            #pragma unroll
            for (int i = 0; i < 6; i++) CP16(dB + bo + i * 16, b + i * 4);
            CP_COMMIT();
        }
        // prefetch next A into registers
        float4 a4[4];
        if (more) {
            const float* Apn = Ap + (blk + 1) * 32;
            #pragma unroll
            for (int q = 0; q < 4; q++)
                a4[q] = aval ? *reinterpret_cast<const float4*>(Apn + q * 4)
                             : make_float4(0.f, 0.f, 0.f, 0.f);
        }

        // ---- compute on buffer `buf` ----
        const uint32_t sA  = sb + buf * BUFB;
        const uint32_t sBB = sA + TILEB;
        const uint32_t aAddrBase = sA + (uint32_t)(m0w + (lane & 15)) * PITCHB
                                      + ((lane >> 4) * 8) * 2;
        const int g = lane >> 3;
        const uint32_t bAddrBase = sBB + (uint32_t)(n0w + ((g >> 1) * 8) + (lane & 7)) * PITCHB
                                       + ((g & 1) * 8) * 2;
        #pragma unroll
        for (int kc = 0; kc < 6; kc++) {
            uint32_t af[4][4], bfr[4][2];
            #pragma unroll
            for (int mi = 0; mi < 4; mi++)
                LDSM4(af[mi][0], af[mi][1], af[mi][2], af[mi][3],
                      aAddrBase + (uint32_t)mi * 16 * PITCHB + kc * 32);
            LDSM4(bfr[0][0], bfr[0][1], bfr[1][0], bfr[1][1], bAddrBase + kc * 32);
            LDSM4(bfr[2][0], bfr[2][1], bfr[3][0], bfr[3][1],
                  bAddrBase + 16 * PITCHB + kc * 32);
            #pragma unroll
            for (int mi = 0; mi < 4; mi++)
                #pragma unroll
                for (int nt = 0; nt < 4; nt++)
                    MMA_BF16(dacc[mi * 4 + nt], af[mi], bfr[nt]);
        }

        if (more) {
            storeA((buf ^ 1) * BUFB, a4);
            CP_WAIT0();
            __syncthreads();
            buf ^= 1;
        }
    }

    // ---- epilogue ----
    #pragma unroll
    for (int mi = 0; mi < 4; mi++) {
        const int r0 = m0 + m0w + mi * 16 + (lane >> 2);
        #pragma unroll
        for (int nt = 0; nt < 4; nt++) {
            const int c = col0 + n0w + nt * 8 + (lane & 3) * 2;
            const float* d = dacc[mi * 4 + nt];
            float b0 = 0.f, b1 = 0.f;
            if (BIAS) { b0 = bias[c]; b1 = bias[c + 1]; }
            #pragma unroll
            for (int hf = 0; hf < 2; hf++) {
                const int r = r0 + hf * 8;
                if (r >= M) continue;
                float v0 = d[hf * 2 + 0] + b0;
                float v1 = d[hf * 2 + 1] + b1;
                if (GELU) {
                    v0 = 0.5f * v0 * (1.0f + erff(v0 * 0.70710678118654752f));
                    v1 = 0.5f * v1 * (1.0f + erff(v1 * 0.70710678118654752f));
                }
                if (RES) {
                    const float2 rv = *reinterpret_cast<const float2*>(
                        res + (size_t)r * N + c);
                    v0 += rv.x; v1 += rv.y;
                }
                *reinterpret_cast<float2*>(C + (size_t)r * N + c) =
                    make_float2(v0, v1);
            }
        }
    }
}

// ---------------- weight expand: W [K,N] f32 -> Wx [N][K*3/2 w] B-pattern ----
__global__ __launch_bounds__(256) void splitw_kernel(
    const float* __restrict__ W, uint32_t* __restrict__ Wx, int K, int N)
{
    const int idx = blockIdx.x * 256 + threadIdx.x;
    const int total = N * (K >> 1);
    if (idx >= total) return;
    const int n = idx % N, p = idx / N;
    const float v0 = W[(size_t)(2 * p) * N + n];
    const float v1 = W[(size_t)(2 * p + 1) * N + n];
    uint32_t w[3];
    packB(v0, v1, w);
    uint32_t* o = Wx + (size_t)n * ((K >> 1) * 3) + p * 3;
    o[0] = w[0]; o[1] = w[1]; o[2] = w[2];
}

// ---------------- LayerNorm: one block per token, 768 = 256*3 ----------------
__global__ __launch_bounds__(256) void ln_kernel(
    const float* __restrict__ x, const float* __restrict__ g,
    const float* __restrict__ b, float* __restrict__ out)
{
    const size_t t = blockIdx.x;
    const float* xr = x + t * DIM;
    const int tid = threadIdx.x;

    float v0 = xr[tid], v1 = xr[tid + 256], v2 = xr[tid + 512];
    float s  = v0 + v1 + v2;
    float ss = v0*v0 + v1*v1 + v2*v2;

    __shared__ float red[16];
    __shared__ float stat[2];
    #pragma unroll
    for (int o = 16; o; o >>= 1) {
        s  += __shfl_xor_sync(0xffffffffu, s,  o);
        ss += __shfl_xor_sync(0xffffffffu, ss, o);
    }
    if ((tid & 31) == 0) { red[tid >> 5] = s; red[(tid >> 5) + 8] = ss; }
    __syncthreads();
    if (tid == 0) {
        float a = 0.f, c = 0.f;
        #pragma unroll
        for (int i = 0; i < 8; i++) { a += red[i]; c += red[i + 8]; }
        float mu = a * (1.0f / DIM);
        float var = c * (1.0f / DIM) - mu * mu;
        stat[0] = mu;
        stat[1] = rsqrtf(var + 1e-5f);
    }
    __syncthreads();
    const float mu = stat[0], inv = stat[1];
    float* orow = out + t * DIM;
    orow[tid      ] = (v0 - mu) * inv * g[tid      ] + b[tid      ];
    orow[tid + 256] = (v1 - mu) * inv * g[tid + 256] + b[tid + 256];
    orow[tid + 512] = (v2 - mu) * inv * g[tid + 512] + b[tid + 512];
}

// ---------------- Fused flash attention (SIMT, R5-proven) ----------------
#define FA_SMEM (3 * 64 * 68 * 4)

__global__ __launch_bounds__(256) void fattn_kernel(
    const float* __restrict__ qkv, float* __restrict__ O)
{
    extern __shared__ float sm[];
    float (*Qs)[68] = reinterpret_cast<float(*)[68]>(sm);
    float (*KP)[68] = reinterpret_cast<float(*)[68]>(sm + 64 * 68);
    float (*Vs)[68] = reinterpret_cast<float(*)[68]>(sm + 2 * 64 * 68);

    const int bh = blockIdx.y;
    const int b = bh / HEADS, h = bh % HEADS;
    const int n0 = blockIdx.x * 64;
    const float* qb = qkv + (size_t)b * SEQ * QKVD + h * HD;
    const float* kb = qb + DIM;
    const float* vb = qb + 2 * DIM;

    const int tid = threadIdx.x;
    const int lr = tid >> 2;
    const int lc = (tid & 3) * 16;
    const int tx = tid & 15, ty = tid >> 4;

    {
        const int n = n0 + lr;
        const float4* src = (n < SEQ)
            ? reinterpret_cast<const float4*>(qb + (size_t)n * QKVD + lc) : nullptr;
        #pragma unroll
        for (int c4 = 0; c4 < 4; c4++) {
            float4 v = src ? src[c4] : make_float4(0.f,0.f,0.f,0.f);
            const int d = lc + c4 * 4;
            Qs[d][lr]=v.x; Qs[d+1][lr]=v.y; Qs[d+2][lr]=v.z; Qs[d+3][lr]=v.w;
        }
    }

    float acc_o[4][4];
    float row_m[4], row_l[4];
    #pragma unroll
    for (int i = 0; i < 4; i++) {
        row_m[i] = -1e30f; row_l[i] = 0.f;
        #pragma unroll
        for (int j = 0; j < 4; j++) acc_o[i][j] = 0.f;
    }

    for (int k0 = 0; k0 < SEQ; k0 += 64) {
        __syncthreads();
        {
            const int m = k0 + lr;
            const float4* srck = (m < SEQ)
                ? reinterpret_cast<const float4*>(kb + (size_t)m * QKVD + lc) : nullptr;
            const float4* srcv = (m < SEQ)
                ? reinterpret_cast<const float4*>(vb + (size_t)m * QKVD + lc) : nullptr;
            #pragma unroll
            for (int c4 = 0; c4 < 4; c4++) {
                float4 v = srck ? srck[c4] : make_float4(0.f,0.f,0.f,0.f);
                const int d = lc + c4 * 4;
                KP[d][lr]=v.x; KP[d+1][lr]=v.y; KP[d+2][lr]=v.z; KP[d+3][lr]=v.w;
                float4 w = srcv ? srcv[c4] : make_float4(0.f,0.f,0.f,0.f);
                *reinterpret_cast<float4*>(&Vs[lr][lc + c4 * 4]) = w;
            }
        }
        __syncthreads();

        float s[4][4];
        #pragma unroll
        for (int i = 0; i < 4; i++)
            #pragma unroll
            for (int j = 0; j < 4; j++) s[i][j] = 0.f;

        #pragma unroll 8
        for (int d = 0; d < 64; d++) {
            float4 ra = *reinterpret_cast<const float4*>(&Qs[d][ty * 4]);
            float4 rb = *reinterpret_cast<const float4*>(&KP[d][tx * 4]);
            float a[4] = {ra.x, ra.y, ra.z, ra.w};
            float bb[4] = {rb.x, rb.y, rb.z, rb.w};
            #pragma unroll
            for (int i = 0; i < 4; i++)
                #pragma unroll
                for (int j = 0; j < 4; j++)
                    s[i][j] = fmaf(a[i], bb[j], s[i][j]);
        }

        #pragma unroll
        for (int i = 0; i < 4; i++)
            #pragma unroll
            for (int j = 0; j < 4; j++) {
                s[i][j] *= 0.125f;
                if (k0 + tx * 4 + j >= SEQ) s[i][j] = -1e30f;
            }

        float f[4];
        #pragma unroll
        for (int i = 0; i < 4; i++) {
            float mt = fmaxf(fmaxf(s[i][0], s[i][1]), fmaxf(s[i][2], s[i][3]));
            #pragma unroll
            for (int o = 1; o < 16; o <<= 1)
                mt = fmaxf(mt, __shfl_xor_sync(0xffffffffu, mt, o, 16));
            const float nm = fmaxf(row_m[i], mt);
            f[i] = __expf(row_m[i] - nm);
            row_m[i] = nm;
            float rs = 0.f;
            #pragma unroll
            for (int j = 0; j < 4; j++) {
                s[i][j] = __expf(s[i][j] - nm);
                rs += s[i][j];
            }
            #pragma unroll
            for (int o = 1; o < 16; o <<= 1)
                rs += __shfl_xor_sync(0xffffffffu, rs, o, 16);
            row_l[i] = row_l[i] * f[i] + rs;
            #pragma unroll
            for (int j = 0; j < 4; j++) acc_o[i][j] *= f[i];
        }

        __syncthreads();
        #pragma unroll
        for (int i = 0; i < 4; i++)
            *reinterpret_cast<float4*>(&KP[ty * 4 + i][tx * 4]) =
                make_float4(s[i][0], s[i][1], s[i][2], s[i][3]);
        __syncthreads();

        #pragma unroll 4
        for (int k = 0; k < 64; k += 4) {
            float4 pa[4], vv[4];
            #pragma unroll
            for (int i = 0; i < 4; i++)
                pa[i] = *reinterpret_cast<const float4*>(&KP[ty * 4 + i][k]);
            #pragma unroll
            for (int kk = 0; kk < 4; kk++)
                vv[kk] = *reinterpret_cast<const float4*>(&Vs[k + kk][tx * 4]);
            #pragma unroll
            for (int i = 0; i < 4; i++) {
                float p[4] = {pa[i].x, pa[i].y, pa[i].z, pa[i].w};
                #pragma unroll
                for (int kk = 0; kk < 4; kk++) {
                    acc_o[i][0] = fmaf(p[kk], vv[kk].x, acc_o[i][0]);
                    acc_o[i][1] = fmaf(p[kk], vv[kk].y, acc_o[i][1]);
                    acc_o[i][2] = fmaf(p[kk], vv[kk].z, acc_o[i][2]);
                    acc_o[i][3] = fmaf(p[kk], vv[kk].w, acc_o[i][3]);
                }
            }
        }
    }

    #pragma unroll
    for (int i = 0; i < 4; i++) {
        const int n = n0 + ty * 4 + i;
        if (n >= SEQ) continue;
        const float inv = 1.0f / row_l[i];
        float4 r = make_float4(acc_o[i][0]*inv, acc_o[i][1]*inv,
                               acc_o[i][2]*inv, acc_o[i][3]*inv);
        *reinterpret_cast<float4*>(
            O + ((size_t)(b * SEQ + n)) * DIM + h * HD + tx * 4) = r;
    }
}

// ---------------- launch ----------------
extern "C" void kernel_launch(void* const* d_in, const int* in_sizes, int n_in,
                              void* d_out, int out_size)
{
    const float* x     = (const float*)d_in[0];
    const float* ln1_g = (const float*)d_in[1];
    const float* ln1_b = (const float*)d_in[2];
    const float* Wqkv  = (const float*)d_in[3];
    const float* Wproj = (const float*)d_in[4];
    const float* bproj = (const float*)d_in[5];
    const float* ln2_g = (const float*)d_in[6];
    const float* ln2_b = (const float*)d_in[7];
    const float* W1    = (const float*)d_in[8];
    const float* b1    = (const float*)d_in[9];
    const float* W2    = (const float*)d_in[10];
    const float* b2    = (const float*)d_in[11];
    float* out = (float*)d_out;

    void* p_arena;
    cudaGetSymbolAddress(&p_arena, g_arena);
    uint32_t* arena = (uint32_t*)p_arena;
    float*    h_buf = (float*)arena;                     // H_F
    float*    x2buf = (float*)(arena + H_F);             // X2_F
    float*    qkvb  = (float*)(arena + H_F + X2_F);      // overlay
    float*    mbuf  = qkvb;                              // overlay
    uint32_t* wqkvx = arena + H_F + X2_F + OVL_F;
    uint32_t* wprojx= wqkvx + WQKV_W;
    uint32_t* w1x   = wprojx + WPROJ_W;
    uint32_t* w2x   = w1x + W1X_W;

    cudaFuncSetAttribute(fattn_kernel,
                         cudaFuncAttributeMaxDynamicSharedMemorySize, FA_SMEM);
    cudaFuncSetAttribute(tcgemm_kernel<false,false,false>,
                         cudaFuncAttributeMaxDynamicSharedMemorySize, GEMM_SMEM);
    cudaFuncSetAttribute(tcgemm_kernel<true,false,true>,
                         cudaFuncAttributeMaxDynamicSharedMemorySize, GEMM_SMEM);
    cudaFuncSetAttribute(tcgemm_kernel<true,true,false>,
                         cudaFuncAttributeMaxDynamicSharedMemorySize, GEMM_SMEM);

    const int MT = (NTOK + 127) / 128;  // 289

    // 0. expand weights (B-pattern), once per launch
    splitw_kernel<<<(QKVD * (DIM/2) + 255) / 256, 256>>>(Wqkv, wqkvx, DIM, QKVD);
    splitw_kernel<<<(DIM * (DIM/2) + 255) / 256, 256>>>(Wproj, wprojx, DIM, DIM);
    splitw_kernel<<<(HIDDEN * (DIM/2) + 255) / 256, 256>>>(W1, w1x, DIM, HIDDEN);
    splitw_kernel<<<(DIM * (HIDDEN/2) + 255) / 256, 256>>>(W2, w2x, HIDDEN, DIM);

    // 1. h = LN1(x)
    ln_kernel<<<NTOK, 256>>>(x, ln1_g, ln1_b, h_buf);
    // 2. qkv = h @ Wqkv
    tcgemm_kernel<false,false,false><<<dim3(QKVD/128, MT), 256, GEMM_SMEM>>>(
        h_buf, wqkvx, nullptr, nullptr, qkvb, NTOK, QKVD, DIM);
    // 3. fused attention -> h_buf
    fattn_kernel<<<dim3(10, BATCH*HEADS), 256, FA_SMEM>>>(qkvb, h_buf);
    // 4. x2 = x + O @ Wproj + bproj
    tcgemm_kernel<true,false,true><<<dim3(DIM/128, MT), 256, GEMM_SMEM>>>(
        h_buf, wprojx, bproj, x, x2buf, NTOK, DIM, DIM);
    // 5. h = LN2(x2)
    ln_kernel<<<NTOK, 256>>>(x2buf, ln2_g, ln2_b, h_buf);
    // 6. m = gelu(h @ W1 + b1)
    tcgemm_kernel<true,true,false><<<dim3(HIDDEN/128, MT), 256, GEMM_SMEM>>>(
        h_buf, w1x, b1, nullptr, mbuf, NTOK, HIDDEN, DIM);
    // 7. out = x2 + m @ W2 + b2
    tcgemm_kernel<true,false,true><<<dim3(DIM/128, MT), 256, GEMM_SMEM>>>(
        mbuf, w2x, b2, x2buf, out, NTOK, DIM, HIDDEN);
}

// round 11
// speedup vs baseline: 1.3518x; 1.1544x over previous
#include <cuda_runtime.h>
#include <math.h>
#include <stdint.h>

#define DIM      768
#define HEADS    12
#define HD       64
#define HIDDEN   3072
#define SEQ      577
#define BATCH    64
#define NTOK     (BATCH*SEQ)  // 36928
#define QKVD     (3*DIM)      // 2304

// ---------------- single scratch arena (overlaid buffers) ----------------
#define ARENA_FLOATS ((size_t)NTOK * DIM * 2 + (size_t)NTOK * HIDDEN)
__device__ __align__(16) float g_arena[ARENA_FLOATS];

// ---------------- helpers ----------------
__device__ __forceinline__ uint32_t smem_u32(const void* p) {
    uint32_t a;
    asm("{ .reg .u64 t; cvta.to.shared.u64 t, %1; cvt.u32.u64 %0, t; }"
        : "=r"(a) : "l"(p));
    return a;
}
// pack (hi,lo) floats -> bf16x2 word, RNE (one HW instruction)
__device__ __forceinline__ uint32_t cvt_bf16x2(float hi, float lo) {
    uint32_t r;
    asm("cvt.rn.bf16x2.f32 %0, %1, %2;" : "=r"(r) : "f"(hi), "f"(lo));
    return r;
}

#define LDSM4(r0, r1, r2, r3, addr) \
    asm volatile("ldmatrix.sync.aligned.m8n8.x4.shared.b16 {%0,%1,%2,%3}, [%4];" \
                 : "=r"(r0), "=r"(r1), "=r"(r2), "=r"(r3) : "r"(addr))

#define MMA_BF16(d, a, b) \
    asm volatile("mma.sync.aligned.m16n8k16.row.col.f32.bf16.bf16.f32 " \
                 "{%0,%1,%2,%3}, {%4,%5,%6,%7}, {%8,%9}, {%0,%1,%2,%3};" \
                 : "+f"((d)[0]), "+f"((d)[1]), "+f"((d)[2]), "+f"((d)[3]) \
                 : "r"((a)[0]), "r"((a)[1]), "r"((a)[2]), "r"((a)[3]), \
                   "r"((b)[0]), "r"((b)[1]))

// ============ bf16-split tensor-core GEMM: 128x128 tile, K-block 32 ==========
// A [M,K] rm, B [K,N] rm, C [M,N]. K%32==0, N%128==0.
// Each fp32 a = ah+al; smem holds K expanded 3x:
//   A slots per k: [ah, ah, al]   B slots per k: [bh, bl, bh]
// so bf16 mma over 96 slots computes ah*bh + ah*bl + al*bh.
#define PITCHB   208                    // bytes per smem row (104 bf16)
#define TILEB    (128 * PITCHB)         // 26624 bytes
#define BUFB     (2 * TILEB)            // A+B = 53248
#define GEMM_SMEM (2 * BUFB)            // 106496

template<bool BIAS, bool GELU, bool RES>
__global__ __launch_bounds__(256) void tcgemm_kernel(
    const float* __restrict__ A, const float* __restrict__ B,
    const float* __restrict__ bias, const float* __restrict__ res,
    float* __restrict__ C, int M, int N, int K)
{
    extern __shared__ char smem[];
    const uint32_t sb = smem_u32(smem);
    const int tid  = threadIdx.x;
    const int lane = tid & 31;
    const int wid  = tid >> 5;
    const int wr = wid >> 2, wc = wid & 3;        // warp grid 2 x 4
    const int m0w = wr * 64, n0w = wc * 32;       // warp tile 64 x 32

    const int m0 = blockIdx.y * 128, col0 = blockIdx.x * 128;

    // ---- loader indices ----
    const int arow = tid >> 1, aseg = tid & 1;            // A: 2 thr/row, 16 floats each
    const int gar = m0 + arow;
    const bool aval = (gar < M);
    const float* Ap = A + (size_t)gar * K + aseg * 16;
    char* sArow = smem + arow * PITCHB + aseg * 96;       // slot 48*aseg -> byte 96*aseg

    const int bn = tid & 127, bkh = (tid >> 7) * 16;      // B: col bn, k-half bkh
    const float* Bp = B + (size_t)bkh * N + col0 + bn;
    char* sBrow = smem + TILEB + bn * PITCHB + bkh * 6;   // slot 3*bkh -> byte 6*bkh

    float dacc[16][4];
    #pragma unroll
    for (int t = 0; t < 16; t++)
        #pragma unroll
        for (int c = 0; c < 4; c++) dacc[t][c] = 0.f;

    const int NBLK = K >> 5;

    // ---- conversion+store of one k-block into buffer bufo ----
    // fast pack: cvt.rn.bf16x2 (RNE, identical numerics to manual split) + PRMT
    auto store_tiles = [&](int bufo, const float4 a4[4], const float bl[16]) {
        char* dst = sArow + bufo;
        #pragma unroll
        for (int q = 0; q < 4; q++) {
            const float v[4] = {a4[q].x, a4[q].y, a4[q].z, a4[q].w};
            #pragma unroll
            for (int pp = 0; pp < 2; pp++) {           // pair (k,k+1)
                const float v0 = v[pp*2], v1 = v[pp*2+1];
                const uint32_t h01 = cvt_bf16x2(v1, v0);     // [h0 | h1<<16]
                const float f0h = __uint_as_float(h01 << 16);
                const float f1h = __uint_as_float(h01 & 0xFFFF0000u);
                const uint32_t l01 = cvt_bf16x2(v1 - f1h, v0 - f0h);
                uint32_t* w = reinterpret_cast<uint32_t*>(dst + (q*2 + pp) * 12);
                w[0] = __byte_perm(h01, h01, 0x1010);  // h0 | h0<<16
                w[1] = __byte_perm(l01, h01, 0x7610);  // l0 | h1<<16
                w[2] = __byte_perm(l01, h01, 0x3276);  // h1 | l1<<16
            }
        }
        char* dstb = sBrow + bufo;
        #pragma unroll
        for (int j = 0; j < 8; j++) {                  // pair (k,k+1)
            const float v0 = bl[2*j], v1 = bl[2*j+1];
            const uint32_t h01 = cvt_bf16x2(v1, v0);
            const float f0h = __uint_as_float(h01 << 16);
            const float f1h = __uint_as_float(h01 & 0xFFFF0000u);
            const uint32_t l01 = cvt_bf16x2(v1 - f1h, v0 - f0h);
            uint32_t* w = reinterpret_cast<uint32_t*>(dstb + j * 12);
            w[0] = __byte_perm(l01, h01, 0x1054);      // h0 | l0<<16
            w[1] = h01;                                 // h0 | h1<<16
            w[2] = __byte_perm(l01, h01, 0x7632);      // l1 | h1<<16
        }
    };

    // ---- preload block 0 ----
    {
        float4 a4[4]; float bl[16];
        #pragma unroll
        for (int q = 0; q < 4; q++)
            a4[q] = aval ? *reinterpret_cast<const float4*>(Ap + q * 4)
                         : make_float4(0.f, 0.f, 0.f, 0.f);
        #pragma unroll
        for (int i = 0; i < 16; i++) bl[i] = Bp[(size_t)i * N];
        store_tiles(0, a4, bl);
    }
    __syncthreads();

    int buf = 0;
    for (int blk = 0; blk < NBLK; blk++) {
        // prefetch next block into registers
        float4 a4[4]; float bl[16];
        const bool more = (blk + 1 < NBLK);
        if (more) {
            const float* Apn = Ap + (blk + 1) * 32;
            const float* Bpn = Bp + (size_t)(blk + 1) * 32 * N;
            #pragma unroll
            for (int q = 0; q < 4; q++)
                a4[q] = aval ? *reinterpret_cast<const float4*>(Apn + q * 4)
                             : make_float4(0.f, 0.f, 0.f, 0.f);
            #pragma unroll
            for (int i = 0; i < 16; i++) bl[i] = Bpn[(size_t)i * N];
        }

        // ---- compute on buffer `buf`: 6 chunks of 16 bf16 slots ----
        const uint32_t sA = sb + buf * BUFB;
        const uint32_t sBB = sA + TILEB;
        const uint32_t aAddrBase = sA + (uint32_t)(m0w + (lane & 15)) * PITCHB
                                      + ((lane >> 4) * 8) * 2;
        const int g = lane >> 3;
        const uint32_t bAddrBase = sBB + (uint32_t)(n0w + ((g >> 1) * 8) + (lane & 7)) * PITCHB
                                       + ((g & 1) * 8) * 2;
        #pragma unroll
        for (int kc = 0; kc < 6; kc++) {
            uint32_t af[4][4], bfr[4][2];
            #pragma unroll
            for (int mi = 0; mi < 4; mi++)
                LDSM4(af[mi][0], af[mi][1], af[mi][2], af[mi][3],
                      aAddrBase + (uint32_t)mi * 16 * PITCHB + kc * 32);
            LDSM4(bfr[0][0], bfr[0][1], bfr[1][0], bfr[1][1], bAddrBase + kc * 32);
            LDSM4(bfr[2][0], bfr[2][1], bfr[3][0], bfr[3][1],
                  bAddrBase + 16 * PITCHB + kc * 32);
            #pragma unroll
            for (int mi = 0; mi < 4; mi++)
                #pragma unroll
                for (int nt = 0; nt < 4; nt++)
                    MMA_BF16(dacc[mi * 4 + nt], af[mi], bfr[nt]);
        }

        if (more) {
            store_tiles((buf ^ 1) * BUFB, a4, bl);
            __syncthreads();
            buf ^= 1;
        }
    }

    // ---- epilogue ----
    #pragma unroll
    for (int mi = 0; mi < 4; mi++) {
        const int r0 = m0 + m0w + mi * 16 + (lane >> 2);
        #pragma unroll
        for (int nt = 0; nt < 4; nt++) {
            const int c = col0 + n0w + nt * 8 + (lane & 3) * 2;
            const float* d = dacc[mi * 4 + nt];
            float b0 = 0.f, b1 = 0.f;
            if (BIAS) { b0 = bias[c]; b1 = bias[c + 1]; }
            #pragma unroll
            for (int half = 0; half < 2; half++) {
                const int r = r0 + half * 8;
                if (r >= M) continue;
                float v0 = d[half * 2 + 0] + b0;
                float v1 = d[half * 2 + 1] + b1;
                if (GELU) {
                    v0 = 0.5f * v0 * (1.0f + erff(v0 * 0.70710678118654752f));
                    v1 = 0.5f * v1 * (1.0f + erff(v1 * 0.70710678118654752f));
                }
                if (RES) {
                    const float2 rv = *reinterpret_cast<const float2*>(
                        res + (size_t)r * N + c);
                    v0 += rv.x; v1 += rv.y;
                }
                *reinterpret_cast<float2*>(C + (size_t)r * N + c) =
                    make_float2(v0, v1);
            }
        }
    }
}

// ---------------- LayerNorm: one block per token, 768 = 256*3 ----------------
__global__ __launch_bounds__(256) void ln_kernel(
    const float* __restrict__ x, const float* __restrict__ g,
    const float* __restrict__ b, float* __restrict__ out)
{
    const size_t t = blockIdx.x;
    const float* xr = x + t * DIM;
    const int tid = threadIdx.x;

    float v0 = xr[tid], v1 = xr[tid + 256], v2 = xr[tid + 512];
    float s  = v0 + v1 + v2;
    float ss = v0*v0 + v1*v1 + v2*v2;

    __shared__ float red[16];
    __shared__ float stat[2];
    #pragma unroll
    for (int o = 16; o; o >>= 1) {
        s  += __shfl_xor_sync(0xffffffffu, s,  o);
        ss += __shfl_xor_sync(0xffffffffu, ss, o);
    }
    if ((tid & 31) == 0) { red[tid >> 5] = s; red[(tid >> 5) + 8] = ss; }
    __syncthreads();
    if (tid == 0) {
        float a = 0.f, c = 0.f;
        #pragma unroll
        for (int i = 0; i < 8; i++) { a += red[i]; c += red[i + 8]; }
        float mu = a * (1.0f / DIM);
        float var = c * (1.0f / DIM) - mu * mu;
        stat[0] = mu;
        stat[1] = rsqrtf(var + 1e-5f);
    }
    __syncthreads();
    const float mu = stat[0], inv = stat[1];
    float* orow = out + t * DIM;
    orow[tid      ] = (v0 - mu) * inv * g[tid      ] + b[tid      ];
    orow[tid + 256] = (v1 - mu) * inv * g[tid + 256] + b[tid + 256];
    orow[tid + 512] = (v2 - mu) * inv * g[tid + 512] + b[tid + 512];
}

// ---------------- Fused flash attention (SIMT, R5-proven) ----------------
#define FA_SMEM (3 * 64 * 68 * 4)

__global__ __launch_bounds__(256) void fattn_kernel(
    const float* __restrict__ qkv, float* __restrict__ O)
{
    extern __shared__ float sm[];
    float (*Qs)[68] = reinterpret_cast<float(*)[68]>(sm);
    float (*KP)[68] = reinterpret_cast<float(*)[68]>(sm + 64 * 68);
    float (*Vs)[68] = reinterpret_cast<float(*)[68]>(sm + 2 * 64 * 68);

    const int bh = blockIdx.y;
    const int b = bh / HEADS, h = bh % HEADS;
    const int n0 = blockIdx.x * 64;
    const float* qb = qkv + (size_t)b * SEQ * QKVD + h * HD;
    const float* kb = qb + DIM;
    const float* vb = qb + 2 * DIM;

    const int tid = threadIdx.x;
    const int lr = tid >> 2;
    const int lc = (tid & 3) * 16;
    const int tx = tid & 15, ty = tid >> 4;

    {
        const int n = n0 + lr;
        const float4* src = (n < SEQ)
            ? reinterpret_cast<const float4*>(qb + (size_t)n * QKVD + lc) : nullptr;
        #pragma unroll
        for (int c4 = 0; c4 < 4; c4++) {
            float4 v = src ? src[c4] : make_float4(0.f,0.f,0.f,0.f);
            const int d = lc + c4 * 4;
            Qs[d][lr]=v.x; Qs[d+1][lr]=v.y; Qs[d+2][lr]=v.z; Qs[d+3][lr]=v.w;
        }
    }

    float acc_o[4][4];
    float row_m[4], row_l[4];
    #pragma unroll
    for (int i = 0; i < 4; i++) {
        row_m[i] = -1e30f; row_l[i] = 0.f;
        #pragma unroll
        for (int j = 0; j < 4; j++) acc_o[i][j] = 0.f;
    }

    for (int k0 = 0; k0 < SEQ; k0 += 64) {
        __syncthreads();
        {
            const int m = k0 + lr;
            const float4* srck = (m < SEQ)
                ? reinterpret_cast<const float4*>(kb + (size_t)m * QKVD + lc) : nullptr;
            const float4* srcv = (m < SEQ)
                ? reinterpret_cast<const float4*>(vb + (size_t)m * QKVD + lc) : nullptr;
            #pragma unroll
            for (int c4 = 0; c4 < 4; c4++) {
                float4 v = srck ? srck[c4] : make_float4(0.f,0.f,0.f,0.f);
                const int d = lc + c4 * 4;
                KP[d][lr]=v.x; KP[d+1][lr]=v.y; KP[d+2][lr]=v.z; KP[d+3][lr]=v.w;
                float4 w = srcv ? srcv[c4] : make_float4(0.f,0.f,0.f,0.f);
                *reinterpret_cast<float4*>(&Vs[lr][lc + c4 * 4]) = w;
            }
        }
        __syncthreads();

        float s[4][4];
        #pragma unroll
        for (int i = 0; i < 4; i++)
            #pragma unroll
            for (int j = 0; j < 4; j++) s[i][j] = 0.f;

        #pragma unroll 8
        for (int d = 0; d < 64; d++) {
            float4 ra = *reinterpret_cast<const float4*>(&Qs[d][ty * 4]);
            float4 rb = *reinterpret_cast<const float4*>(&KP[d][tx * 4]);
            float a[4] = {ra.x, ra.y, ra.z, ra.w};
            float bb[4] = {rb.x, rb.y, rb.z, rb.w};
            #pragma unroll
            for (int i = 0; i < 4; i++)
                #pragma unroll
                for (int j = 0; j < 4; j++)
                    s[i][j] = fmaf(a[i], bb[j], s[i][j]);
        }

        #pragma unroll
        for (int i = 0; i < 4; i++)
            #pragma unroll
            for (int j = 0; j < 4; j++) {
                s[i][j] *= 0.125f;
                if (k0 + tx * 4 + j >= SEQ) s[i][j] = -1e30f;
            }

        float f[4];
        #pragma unroll
        for (int i = 0; i < 4; i++) {
            float mt = fmaxf(fmaxf(s[i][0], s[i][1]), fmaxf(s[i][2], s[i][3]));
            #pragma unroll
            for (int o = 1; o < 16; o <<= 1)
                mt = fmaxf(mt, __shfl_xor_sync(0xffffffffu, mt, o, 16));
            const float nm = fmaxf(row_m[i], mt);
            f[i] = __expf(row_m[i] - nm);
            row_m[i] = nm;
            float rs = 0.f;
            #pragma unroll
            for (int j = 0; j < 4; j++) {
                s[i][j] = __expf(s[i][j] - nm);
                rs += s[i][j];
            }
            #pragma unroll
            for (int o = 1; o < 16; o <<= 1)
                rs += __shfl_xor_sync(0xffffffffu, rs, o, 16);
            row_l[i] = row_l[i] * f[i] + rs;
            #pragma unroll
            for (int j = 0; j < 4; j++) acc_o[i][j] *= f[i];
        }

        __syncthreads();
        #pragma unroll
        for (int i = 0; i < 4; i++)
            *reinterpret_cast<float4*>(&KP[ty * 4 + i][tx * 4]) =
                make_float4(s[i][0], s[i][1], s[i][2], s[i][3]);
        __syncthreads();

        #pragma unroll 4
        for (int k = 0; k < 64; k += 4) {
            float4 pa[4], vv[4];
            #pragma unroll
            for (int i = 0; i < 4; i++)
                pa[i] = *reinterpret_cast<const float4*>(&KP[ty * 4 + i][k]);
            #pragma unroll
            for (int kk = 0; kk < 4; kk++)
                vv[kk] = *reinterpret_cast<const float4*>(&Vs[k + kk][tx * 4]);
            #pragma unroll
            for (int i = 0; i < 4; i++) {
                float p[4] = {pa[i].x, pa[i].y, pa[i].z, pa[i].w};
                #pragma unroll
                for (int kk = 0; kk < 4; kk++) {
                    acc_o[i][0] = fmaf(p[kk], vv[kk].x, acc_o[i][0]);
                    acc_o[i][1] = fmaf(p[kk], vv[kk].y, acc_o[i][1]);
                    acc_o[i][2] = fmaf(p[kk], vv[kk].z, acc_o[i][2]);
                    acc_o[i][3] = fmaf(p[kk], vv[kk].w, acc_o[i][3]);
                }
            }
        }
    }

    #pragma unroll
    for (int i = 0; i < 4; i++) {
        const int n = n0 + ty * 4 + i;
        if (n >= SEQ) continue;
        const float inv = 1.0f / row_l[i];
        float4 r = make_float4(acc_o[i][0]*inv, acc_o[i][1]*inv,
                               acc_o[i][2]*inv, acc_o[i][3]*inv);
        *reinterpret_cast<float4*>(
            O + ((size_t)(b * SEQ + n)) * DIM + h * HD + tx * 4) = r;
    }
}

// ---------------- launch ----------------
extern "C" void kernel_launch(void* const* d_in, const int* in_sizes, int n_in,
                              void* d_out, int out_size)
{
    const float* x     = (const float*)d_in[0];
    const float* ln1_g = (const float*)d_in[1];
    const float* ln1_b = (const float*)d_in[2];
    const float* Wqkv  = (const float*)d_in[3];
    const float* Wproj = (const float*)d_in[4];
    const float* bproj = (const float*)d_in[5];
    const float* ln2_g = (const float*)d_in[6];
    const float* ln2_b = (const float*)d_in[7];
    const float* W1    = (const float*)d_in[8];
    const float* b1    = (const float*)d_in[9];
    const float* W2    = (const float*)d_in[10];
    const float* b2    = (const float*)d_in[11];
    float* out = (float*)d_out;

    void* p_arena;
    cudaGetSymbolAddress(&p_arena, g_arena);
    float* arena = (float*)p_arena;
    float* h_buf = arena;                               // NTOK*DIM
    float* x2buf = arena + (size_t)NTOK * DIM;          // NTOK*DIM
    float* qkvb  = arena + (size_t)NTOK * DIM * 2;      // NTOK*QKVD (overlaid)
    float* mbuf  = qkvb;                                // NTOK*HIDDEN (overlaid)

    cudaFuncSetAttribute(fattn_kernel,
                         cudaFuncAttributeMaxDynamicSharedMemorySize, FA_SMEM);
    cudaFuncSetAttribute(tcgemm_kernel<false,false,false>,
                         cudaFuncAttributeMaxDynamicSharedMemorySize, GEMM_SMEM);
    cudaFuncSetAttribute(tcgemm_kernel<true,false,true>,
                         cudaFuncAttributeMaxDynamicSharedMemorySize, GEMM_SMEM);
    cudaFuncSetAttribute(tcgemm_kernel<true,true,false>,
                         cudaFuncAttributeMaxDynamicSharedMemorySize, GEMM_SMEM);

    const int MT = (NTOK + 127) / 128;  // 289

    // 1. h = LN1(x)
    ln_kernel<<<NTOK, 256>>>(x, ln1_g, ln1_b, h_buf);
    // 2. qkv = h @ Wqkv
    tcgemm_kernel<false,false,false><<<dim3(QKVD/128, MT), 256, GEMM_SMEM>>>(
        h_buf, Wqkv, nullptr, nullptr, qkvb, NTOK, QKVD, DIM);
    // 3. fused attention -> h_buf (reused; qkv dead afterwards)
    fattn_kernel<<<dim3(10, BATCH*HEADS), 256, FA_SMEM>>>(qkvb, h_buf);
    // 4. x2 = x + O @ Wproj + bproj
    tcgemm_kernel<true,false,true><<<dim3(DIM/128, MT), 256, GEMM_SMEM>>>(
        h_buf, Wproj, bproj, x, x2buf, NTOK, DIM, DIM);
    // 5. h = LN2(x2)
    ln_kernel<<<NTOK, 256>>>(x2buf, ln2_g, ln2_b, h_buf);
    // 6. m = gelu(h @ W1 + b1)
    tcgemm_kernel<true,true,false><<<dim3(HIDDEN/128, MT), 256, GEMM_SMEM>>>(
        h_buf, W1, b1, nullptr, mbuf, NTOK, HIDDEN, DIM);
    // 7. out = x2 + m @ W2 + b2
    tcgemm_kernel<true,false,true><<<dim3(DIM/128, MT), 256, GEMM_SMEM>>>(
        mbuf, W2, b2, x2buf, out, NTOK, DIM, HIDDEN);
}

// round 12
// speedup vs baseline: 1.5187x; 1.1234x over previous
#include <cuda_runtime.h>
#include <math.h>
#include <stdint.h>

#define DIM      768
#define HEADS    12
#define HD       64
#define HIDDEN   3072
#define SEQ      577
#define BATCH    64
#define NTOK     (BATCH*SEQ)  // 36928
#define QKVD     (3*DIM)      // 2304

// ---------------- single scratch arena (overlaid buffers) ----------------
#define ARENA_FLOATS ((size_t)NTOK * DIM * 2 + (size_t)NTOK * HIDDEN)
__device__ __align__(16) float g_arena[ARENA_FLOATS];

// ---------------- helpers ----------------
__device__ __forceinline__ uint32_t smem_u32(const void* p) {
    uint32_t a;
    asm("{ .reg .u64 t; cvta.to.shared.u64 t, %1; cvt.u32.u64 %0, t; }"
        : "=r"(a) : "l"(p));
    return a;
}
// pack (hi,lo) floats -> bf16x2 word, RNE (one HW instruction)
__device__ __forceinline__ uint32_t cvt_bf16x2(float hi, float lo) {
    uint32_t r;
    asm("cvt.rn.bf16x2.f32 %0, %1, %2;" : "=r"(r) : "f"(hi), "f"(lo));
    return r;
}

#define LDSM4(r0, r1, r2, r3, addr) \
    asm volatile("ldmatrix.sync.aligned.m8n8.x4.shared.b16 {%0,%1,%2,%3}, [%4];" \
                 : "=r"(r0), "=r"(r1), "=r"(r2), "=r"(r3) : "r"(addr))

#define MMA_BF16(d, a, b) \
    asm volatile("mma.sync.aligned.m16n8k16.row.col.f32.bf16.bf16.f32 " \
                 "{%0,%1,%2,%3}, {%4,%5,%6,%7}, {%8,%9}, {%0,%1,%2,%3};" \
                 : "+f"((d)[0]), "+f"((d)[1]), "+f"((d)[2]), "+f"((d)[3]) \
                 : "r"((a)[0]), "r"((a)[1]), "r"((a)[2]), "r"((a)[3]), \
                   "r"((b)[0]), "r"((b)[1]))

// ============ bf16-split tensor-core GEMM: 128x256 tile, K-block 32 ==========
// A [M,K] rm, B [K,N] rm, C [M,N]. K%32==0, N%256==0.
// Each fp32 a = ah+al; smem holds K expanded 3x:
//   A slots per k: [ah, ah, al]   B slots per k: [bh, bl, bh]
// 8 warps in 2x4 grid, 64x64 per warp.
#define PITCHB   208                    // bytes per smem row (104 bf16)
#define ATILE    (128 * PITCHB)         // 26624
#define BTILE    (256 * PITCHB)         // 53248
#define BUFB     (ATILE + BTILE)        // 79872
#define GEMM_SMEM (2 * BUFB)            // 159744

template<bool BIAS, bool GELU, bool RES>
__global__ __launch_bounds__(256, 1) void tcgemm_kernel(
    const float* __restrict__ A, const float* __restrict__ B,
    const float* __restrict__ bias, const float* __restrict__ res,
    float* __restrict__ C, int M, int N, int K)
{
    extern __shared__ char smem[];
    const uint32_t sb = smem_u32(smem);
    const int tid  = threadIdx.x;
    const int lane = tid & 31;
    const int wid  = tid >> 5;
    const int wr = wid >> 2, wc = wid & 3;        // warp grid 2 x 4
    const int m0w = wr * 64, n0w = wc * 64;       // warp tile 64 x 64

    const int m0 = blockIdx.y * 128, col0 = blockIdx.x * 256;

    // ---- A loader: row = tid/2, seg = tid&1 covers 16 floats -> 96 B ----
    const int arow = tid >> 1, aseg = tid & 1;
    const int gar = m0 + arow;
    const bool aval = (gar < M);
    const float* Ap = A + (size_t)gar * K + aseg * 16;
    char* sArow = smem + arow * PITCHB + aseg * 96;

    // ---- B loader: col bn = tid, all 32 k values (strided by N) ----
    const int bn = tid;
    const float* Bp = B + col0 + bn;
    char* sBrow = smem + ATILE + bn * PITCHB;

    float dacc[32][4];
    #pragma unroll
    for (int t = 0; t < 32; t++)
        #pragma unroll
        for (int c = 0; c < 4; c++) dacc[t][c] = 0.f;

    const int NBLK = K >> 5;

    // ---- conversion+store of one k-block into buffer bufo ----
    auto store_tiles = [&](int bufo, const float4 a4[4], const float bl[32]) {
        char* dst = sArow + bufo;
        #pragma unroll
        for (int q = 0; q < 4; q++) {
            const float v[4] = {a4[q].x, a4[q].y, a4[q].z, a4[q].w};
            #pragma unroll
            for (int pp = 0; pp < 2; pp++) {           // pair (k,k+1)
                const float v0 = v[pp*2], v1 = v[pp*2+1];
                const uint32_t h01 = cvt_bf16x2(v1, v0);     // [h0 | h1<<16]
                const float f0h = __uint_as_float(h01 << 16);
                const float f1h = __uint_as_float(h01 & 0xFFFF0000u);
                const uint32_t l01 = cvt_bf16x2(v1 - f1h, v0 - f0h);
                uint32_t* w = reinterpret_cast<uint32_t*>(dst + (q*2 + pp) * 12);
                w[0] = __byte_perm(h01, h01, 0x1010);  // h0 | h0<<16
                w[1] = __byte_perm(l01, h01, 0x7610);  // l0 | h1<<16
                w[2] = __byte_perm(l01, h01, 0x3276);  // h1 | l1<<16
            }
        }
        char* dstb = sBrow + bufo;
        #pragma unroll
        for (int j = 0; j < 16; j++) {                 // pair (k,k+1)
            const float v0 = bl[2*j], v1 = bl[2*j+1];
            const uint32_t h01 = cvt_bf16x2(v1, v0);
            const float f0h = __uint_as_float(h01 << 16);
            const float f1h = __uint_as_float(h01 & 0xFFFF0000u);
            const uint32_t l01 = cvt_bf16x2(v1 - f1h, v0 - f0h);
            uint32_t* w = reinterpret_cast<uint32_t*>(dstb + j * 12);
            w[0] = __byte_perm(l01, h01, 0x1054);      // h0 | l0<<16
            w[1] = h01;                                 // h0 | h1<<16
            w[2] = __byte_perm(l01, h01, 0x7632);      // l1 | h1<<16
        }
    };

    // ---- preload block 0 ----
    {
        float4 a4[4]; float bl[32];
        #pragma unroll
        for (int q = 0; q < 4; q++)
            a4[q] = aval ? *reinterpret_cast<const float4*>(Ap + q * 4)
                         : make_float4(0.f, 0.f, 0.f, 0.f);
        #pragma unroll
        for (int i = 0; i < 32; i++) bl[i] = Bp[(size_t)i * N];
        store_tiles(0, a4, bl);
    }
    __syncthreads();

    int buf = 0;
    for (int blk = 0; blk < NBLK; blk++) {
        // prefetch next block into registers
        float4 a4[4]; float bl[32];
        const bool more = (blk + 1 < NBLK);
        if (more) {
            const float* Apn = Ap + (blk + 1) * 32;
            const float* Bpn = Bp + (size_t)(blk + 1) * 32 * N;
            #pragma unroll
            for (int q = 0; q < 4; q++)
                a4[q] = aval ? *reinterpret_cast<const float4*>(Apn + q * 4)
                             : make_float4(0.f, 0.f, 0.f, 0.f);
            #pragma unroll
            for (int i = 0; i < 32; i++) bl[i] = Bpn[(size_t)i * N];
        }

        // ---- compute on buffer `buf`: 6 chunks of 16 bf16 slots ----
        const uint32_t sA  = sb + buf * BUFB;
        const uint32_t sBB = sA + ATILE;
        const uint32_t aAddrBase = sA + (uint32_t)(m0w + (lane & 15)) * PITCHB
                                      + ((lane >> 4) * 8) * 2;
        const int g = lane >> 3;
        const uint32_t bAddrBase = sBB + (uint32_t)(n0w + ((g >> 1) * 8) + (lane & 7)) * PITCHB
                                       + ((g & 1) * 8) * 2;
        #pragma unroll
        for (int kc = 0; kc < 6; kc++) {
            uint32_t af[4][4], bfr[8][2];
            #pragma unroll
            for (int mi = 0; mi < 4; mi++)
                LDSM4(af[mi][0], af[mi][1], af[mi][2], af[mi][3],
                      aAddrBase + (uint32_t)mi * 16 * PITCHB + kc * 32);
            #pragma unroll
            for (int p = 0; p < 4; p++)
                LDSM4(bfr[2*p][0], bfr[2*p][1], bfr[2*p+1][0], bfr[2*p+1][1],
                      bAddrBase + (uint32_t)p * 16 * PITCHB + kc * 32);
            #pragma unroll
            for (int mi = 0; mi < 4; mi++)
                #pragma unroll
                for (int nt = 0; nt < 8; nt++)
                    MMA_BF16(dacc[mi * 8 + nt], af[mi], bfr[nt]);
        }

        if (more) {
            store_tiles((buf ^ 1) * BUFB, a4, bl);
            __syncthreads();
            buf ^= 1;
        }
    }

    // ---- epilogue ----
    #pragma unroll
    for (int mi = 0; mi < 4; mi++) {
        const int r0 = m0 + m0w + mi * 16 + (lane >> 2);
        #pragma unroll
        for (int nt = 0; nt < 8; nt++) {
            const int c = col0 + n0w + nt * 8 + (lane & 3) * 2;
            const float* d = dacc[mi * 8 + nt];
            float b0 = 0.f, b1 = 0.f;
            if (BIAS) { b0 = bias[c]; b1 = bias[c + 1]; }
            #pragma unroll
            for (int half = 0; half < 2; half++) {
                const int r = r0 + half * 8;
                if (r >= M) continue;
                float v0 = d[half * 2 + 0] + b0;
                float v1 = d[half * 2 + 1] + b1;
                if (GELU) {
                    v0 = 0.5f * v0 * (1.0f + erff(v0 * 0.70710678118654752f));
                    v1 = 0.5f * v1 * (1.0f + erff(v1 * 0.70710678118654752f));
                }
                if (RES) {
                    const float2 rv = *reinterpret_cast<const float2*>(
                        res + (size_t)r * N + c);
                    v0 += rv.x; v1 += rv.y;
                }
                *reinterpret_cast<float2*>(C + (size_t)r * N + c) =
                    make_float2(v0, v1);
            }
        }
    }
}

// ---------------- LayerNorm: one block per token, 768 = 256*3 ----------------
__global__ __launch_bounds__(256) void ln_kernel(
    const float* __restrict__ x, const float* __restrict__ g,
    const float* __restrict__ b, float* __restrict__ out)
{
    const size_t t = blockIdx.x;
    const float* xr = x + t * DIM;
    const int tid = threadIdx.x;

    float v0 = xr[tid], v1 = xr[tid + 256], v2 = xr[tid + 512];
    float s  = v0 + v1 + v2;
    float ss = v0*v0 + v1*v1 + v2*v2;

    __shared__ float red[16];
    __shared__ float stat[2];
    #pragma unroll
    for (int o = 16; o; o >>= 1) {
        s  += __shfl_xor_sync(0xffffffffu, s,  o);
        ss += __shfl_xor_sync(0xffffffffu, ss, o);
    }
    if ((tid & 31) == 0) { red[tid >> 5] = s; red[(tid >> 5) + 8] = ss; }
    __syncthreads();
    if (tid == 0) {
        float a = 0.f, c = 0.f;
        #pragma unroll
        for (int i = 0; i < 8; i++) { a += red[i]; c += red[i + 8]; }
        float mu = a * (1.0f / DIM);
        float var = c * (1.0f / DIM) - mu * mu;
        stat[0] = mu;
        stat[1] = rsqrtf(var + 1e-5f);
    }
    __syncthreads();
    const float mu = stat[0], inv = stat[1];
    float* orow = out + t * DIM;
    orow[tid      ] = (v0 - mu) * inv * g[tid      ] + b[tid      ];
    orow[tid + 256] = (v1 - mu) * inv * g[tid + 256] + b[tid + 256];
    orow[tid + 512] = (v2 - mu) * inv * g[tid + 512] + b[tid + 512];
}

// ---------------- Fused flash attention (SIMT, R5-proven) ----------------
#define FA_SMEM (3 * 64 * 68 * 4)

__global__ __launch_bounds__(256) void fattn_kernel(
    const float* __restrict__ qkv, float* __restrict__ O)
{
    extern __shared__ float sm[];
    float (*Qs)[68] = reinterpret_cast<float(*)[68]>(sm);
    float (*KP)[68] = reinterpret_cast<float(*)[68]>(sm + 64 * 68);
    float (*Vs)[68] = reinterpret_cast<float(*)[68]>(sm + 2 * 64 * 68);

    const int bh = blockIdx.y;
    const int b = bh / HEADS, h = bh % HEADS;
    const int n0 = blockIdx.x * 64;
    const float* qb = qkv + (size_t)b * SEQ * QKVD + h * HD;
    const float* kb = qb + DIM;
    const float* vb = qb + 2 * DIM;

    const int tid = threadIdx.x;
    const int lr = tid >> 2;
    const int lc = (tid & 3) * 16;
    const int tx = tid & 15, ty = tid >> 4;

    {
        const int n = n0 + lr;
        const float4* src = (n < SEQ)
            ? reinterpret_cast<const float4*>(qb + (size_t)n * QKVD + lc) : nullptr;
        #pragma unroll
        for (int c4 = 0; c4 < 4; c4++) {
            float4 v = src ? src[c4] : make_float4(0.f,0.f,0.f,0.f);
            const int d = lc + c4 * 4;
            Qs[d][lr]=v.x; Qs[d+1][lr]=v.y; Qs[d+2][lr]=v.z; Qs[d+3][lr]=v.w;
        }
    }

    float acc_o[4][4];
    float row_m[4], row_l[4];
    #pragma unroll
    for (int i = 0; i < 4; i++) {
        row_m[i] = -1e30f; row_l[i] = 0.f;
        #pragma unroll
        for (int j = 0; j < 4; j++) acc_o[i][j] = 0.f;
    }

    for (int k0 = 0; k0 < SEQ; k0 += 64) {
        __syncthreads();
        {
            const int m = k0 + lr;
            const float4* srck = (m < SEQ)
                ? reinterpret_cast<const float4*>(kb + (size_t)m * QKVD + lc) : nullptr;
            const float4* srcv = (m < SEQ)
                ? reinterpret_cast<const float4*>(vb + (size_t)m * QKVD + lc) : nullptr;
            #pragma unroll
            for (int c4 = 0; c4 < 4; c4++) {
                float4 v = srck ? srck[c4] : make_float4(0.f,0.f,0.f,0.f);
                const int d = lc + c4 * 4;
                KP[d][lr]=v.x; KP[d+1][lr]=v.y; KP[d+2][lr]=v.z; KP[d+3][lr]=v.w;
                float4 w = srcv ? srcv[c4] : make_float4(0.f,0.f,0.f,0.f);
                *reinterpret_cast<float4*>(&Vs[lr][lc + c4 * 4]) = w;
            }
        }
        __syncthreads();

        float s[4][4];
        #pragma unroll
        for (int i = 0; i < 4; i++)
            #pragma unroll
            for (int j = 0; j < 4; j++) s[i][j] = 0.f;

        #pragma unroll 8
        for (int d = 0; d < 64; d++) {
            float4 ra = *reinterpret_cast<const float4*>(&Qs[d][ty * 4]);
            float4 rb = *reinterpret_cast<const float4*>(&KP[d][tx * 4]);
            float a[4] = {ra.x, ra.y, ra.z, ra.w};
            float bb[4] = {rb.x, rb.y, rb.z, rb.w};
            #pragma unroll
            for (int i = 0; i < 4; i++)
                #pragma unroll
                for (int j = 0; j < 4; j++)
                    s[i][j] = fmaf(a[i], bb[j], s[i][j]);
        }

        #pragma unroll
        for (int i = 0; i < 4; i++)
            #pragma unroll
            for (int j = 0; j < 4; j++) {
                s[i][j] *= 0.125f;
                if (k0 + tx * 4 + j >= SEQ) s[i][j] = -1e30f;
            }

        float f[4];
        #pragma unroll
        for (int i = 0; i < 4; i++) {
            float mt = fmaxf(fmaxf(s[i][0], s[i][1]), fmaxf(s[i][2], s[i][3]));
            #pragma unroll
            for (int o = 1; o < 16; o <<= 1)
                mt = fmaxf(mt, __shfl_xor_sync(0xffffffffu, mt, o, 16));
            const float nm = fmaxf(row_m[i], mt);
            f[i] = __expf(row_m[i] - nm);
            row_m[i] = nm;
            float rs = 0.f;
            #pragma unroll
            for (int j = 0; j < 4; j++) {
                s[i][j] = __expf(s[i][j] - nm);
                rs += s[i][j];
            }
            #pragma unroll
            for (int o = 1; o < 16; o <<= 1)
                rs += __shfl_xor_sync(0xffffffffu, rs, o, 16);
            row_l[i] = row_l[i] * f[i] + rs;
            #pragma unroll
            for (int j = 0; j < 4; j++) acc_o[i][j] *= f[i];
        }

        __syncthreads();
        #pragma unroll
        for (int i = 0; i < 4; i++)
            *reinterpret_cast<float4*>(&KP[ty * 4 + i][tx * 4]) =
                make_float4(s[i][0], s[i][1], s[i][2], s[i][3]);
        __syncthreads();

        #pragma unroll 4
        for (int k = 0; k < 64; k += 4) {
            float4 pa[4], vv[4];
            #pragma unroll
            for (int i = 0; i < 4; i++)
                pa[i] = *reinterpret_cast<const float4*>(&KP[ty * 4 + i][k]);
            #pragma unroll
            for (int kk = 0; kk < 4; kk++)
                vv[kk] = *reinterpret_cast<const float4*>(&Vs[k + kk][tx * 4]);
            #pragma unroll
            for (int i = 0; i < 4; i++) {
                float p[4] = {pa[i].x, pa[i].y, pa[i].z, pa[i].w};
                #pragma unroll
                for (int kk = 0; kk < 4; kk++) {
                    acc_o[i][0] = fmaf(p[kk], vv[kk].x, acc_o[i][0]);
                    acc_o[i][1] = fmaf(p[kk], vv[kk].y, acc_o[i][1]);
                    acc_o[i][2] = fmaf(p[kk], vv[kk].z, acc_o[i][2]);
                    acc_o[i][3] = fmaf(p[kk], vv[kk].w, acc_o[i][3]);
                }
            }
        }
    }

    #pragma unroll
    for (int i = 0; i < 4; i++) {
        const int n = n0 + ty * 4 + i;
        if (n >= SEQ) continue;
        const float inv = 1.0f / row_l[i];
        float4 r = make_float4(acc_o[i][0]*inv, acc_o[i][1]*inv,
                               acc_o[i][2]*inv, acc_o[i][3]*inv);
        *reinterpret_cast<float4*>(
            O + ((size_t)(b * SEQ + n)) * DIM + h * HD + tx * 4) = r;
    }
}

// ---------------- launch ----------------
extern "C" void kernel_launch(void* const* d_in, const int* in_sizes, int n_in,
                              void* d_out, int out_size)
{
    const float* x     = (const float*)d_in[0];
    const float* ln1_g = (const float*)d_in[1];
    const float* ln1_b = (const float*)d_in[2];
    const float* Wqkv  = (const float*)d_in[3];
    const float* Wproj = (const float*)d_in[4];
    const float* bproj = (const float*)d_in[5];
    const float* ln2_g = (const float*)d_in[6];
    const float* ln2_b = (const float*)d_in[7];
    const float* W1    = (const float*)d_in[8];
    const float* b1    = (const float*)d_in[9];
    const float* W2    = (const float*)d_in[10];
    const float* b2    = (const float*)d_in[11];
    float* out = (float*)d_out;

    void* p_arena;
    cudaGetSymbolAddress(&p_arena, g_arena);
    float* arena = (float*)p_arena;
    float* h_buf = arena;                               // NTOK*DIM
    float* x2buf = arena + (size_t)NTOK * DIM;          // NTOK*DIM
    float* qkvb  = arena + (size_t)NTOK * DIM * 2;      // NTOK*QKVD (overlaid)
    float* mbuf  = qkvb;                                // NTOK*HIDDEN (overlaid)

    cudaFuncSetAttribute(fattn_kernel,
                         cudaFuncAttributeMaxDynamicSharedMemorySize, FA_SMEM);
    cudaFuncSetAttribute(tcgemm_kernel<false,false,false>,
                         cudaFuncAttributeMaxDynamicSharedMemorySize, GEMM_SMEM);
    cudaFuncSetAttribute(tcgemm_kernel<true,false,true>,
                         cudaFuncAttributeMaxDynamicSharedMemorySize, GEMM_SMEM);
    cudaFuncSetAttribute(tcgemm_kernel<true,true,false>,
                         cudaFuncAttributeMaxDynamicSharedMemorySize, GEMM_SMEM);

    const int MT = (NTOK + 127) / 128;  // 289

    // 1. h = LN1(x)
    ln_kernel<<<NTOK, 256>>>(x, ln1_g, ln1_b, h_buf);
    // 2. qkv = h @ Wqkv
    tcgemm_kernel<false,false,false><<<dim3(QKVD/256, MT), 256, GEMM_SMEM>>>(
        h_buf, Wqkv, nullptr, nullptr, qkvb, NTOK, QKVD, DIM);
    // 3. fused attention -> h_buf (reused; qkv dead afterwards)
    fattn_kernel<<<dim3(10, BATCH*HEADS), 256, FA_SMEM>>>(qkvb, h_buf);
    // 4. x2 = x + O @ Wproj + bproj
    tcgemm_kernel<true,false,true><<<dim3(DIM/256, MT), 256, GEMM_SMEM>>>(
        h_buf, Wproj, bproj, x, x2buf, NTOK, DIM, DIM);
    // 5. h = LN2(x2)
    ln_kernel<<<NTOK, 256>>>(x2buf, ln2_g, ln2_b, h_buf);
    // 6. m = gelu(h @ W1 + b1)
    tcgemm_kernel<true,true,false><<<dim3(HIDDEN/256, MT), 256, GEMM_SMEM>>>(
        h_buf, W1, b1, nullptr, mbuf, NTOK, HIDDEN, DIM);
    // 7. out = x2 + m @ W2 + b2
    tcgemm_kernel<true,false,true><<<dim3(DIM/256, MT), 256, GEMM_SMEM>>>(
        mbuf, W2, b2, x2buf, out, NTOK, DIM, HIDDEN);
}